// round 12
// baseline (speedup 1.0000x reference)
#include <cuda_runtime.h>
#include <cstdint>
#include <math.h>

#define K_DIM 1024
#define N_EXPERTS 64
#define BM 128
#define KCHUNK 8
#define NLOCAL 64                  // chunks per group (512 K each, 8 per chunk)
#define XS_STRIDE 132              // [k][token] floats
#define WS_STRIDE 68               // [k][expert] floats
#define XS_FLOATS (KCHUNK * XS_STRIDE)                 // 1056
#define GRP_FLOATS (KCHUNK * (XS_STRIDE + WS_STRIDE))  // 1600 floats per stage
#define LG_STRIDE 68
#define SMEM_FLOATS 8704           // max(2 groups * 2 stages * 1600 = 6400, 128*68 = 8704)
#define FULL 0xffffffffu

#define GBAR(id) asm volatile("bar.sync %0, 128;" :: "r"(id) : "memory")

__global__ __launch_bounds__(256, 2)
void router_splitk2_kernel(const float* __restrict__ x,
                           const float* __restrict__ Wm,
                           const float* __restrict__ bias,
                           float* __restrict__ out,
                           int num_tokens) {
    extern __shared__ float smem[];
    const int tid  = threadIdx.x;
    const int gid  = tid >> 7;          // k-split group 0/1
    const int gtid = tid & 127;
    const int bm   = blockIdx.x * BM;
    const int kbase = gid * (K_DIM / 2);

    float* gbase = smem + gid * 2 * GRP_FLOATS;

    // loader mapping: kq = k-granule 0/1, row = 0..63
    const int kq  = gtid & 1;
    const int row = gtid >> 1;

    // compute mapping: txk = expert oct 0..7, tym = token oct 0..15
    const int txk = gtid & 7;
    const int tym = gtid >> 3;

    float4 xv0, xv1, wv;
    auto ldg_chunk = [&](int c) {
        const int ko = kbase + c * KCHUNK + kq * 4;
        xv0 = __ldg((const float4*)(x + (size_t)(bm + row) * K_DIM + ko));
        xv1 = __ldg((const float4*)(x + (size_t)(bm + row + 64) * K_DIM + ko));
        wv  = __ldg((const float4*)(Wm + (size_t)row * K_DIM + ko));
    };
    auto sts_chunk = [&](int buf) {
        float* xs = gbase + buf * GRP_FLOATS;
        float* ws = xs + XS_FLOATS;
        const int kb = kq * 4;
        xs[(kb + 0) * XS_STRIDE + row] = xv0.x;
        xs[(kb + 1) * XS_STRIDE + row] = xv0.y;
        xs[(kb + 2) * XS_STRIDE + row] = xv0.z;
        xs[(kb + 3) * XS_STRIDE + row] = xv0.w;
        xs[(kb + 0) * XS_STRIDE + row + 64] = xv1.x;
        xs[(kb + 1) * XS_STRIDE + row + 64] = xv1.y;
        xs[(kb + 2) * XS_STRIDE + row + 64] = xv1.z;
        xs[(kb + 3) * XS_STRIDE + row + 64] = xv1.w;
        ws[(kb + 0) * WS_STRIDE + row] = wv.x;
        ws[(kb + 1) * WS_STRIDE + row] = wv.y;
        ws[(kb + 2) * WS_STRIDE + row] = wv.z;
        ws[(kb + 3) * WS_STRIDE + row] = wv.w;
    };

    float acc[8][8];
    #pragma unroll
    for (int i = 0; i < 8; ++i)
        #pragma unroll
        for (int j = 0; j < 8; ++j) acc[i][j] = 0.0f;

    const int barid = 1 + gid;

    ldg_chunk(0);
    sts_chunk(0);
    GBAR(barid);

    #pragma unroll 1
    for (int c = 0; c < NLOCAL; ++c) {
        if (c + 1 < NLOCAL) ldg_chunk(c + 1);

        const float* xs = gbase + (c & 1) * GRP_FLOATS;
        const float* ws = xs + XS_FLOATS;

        #pragma unroll
        for (int k = 0; k < KCHUNK; ++k) {
            const float4 a0 = *(const float4*)&xs[k * XS_STRIDE + tym * 8];
            const float4 a1 = *(const float4*)&xs[k * XS_STRIDE + tym * 8 + 4];
            const float4 b0 = *(const float4*)&ws[k * WS_STRIDE + txk * 8];
            const float4 b1 = *(const float4*)&ws[k * WS_STRIDE + txk * 8 + 4];
            const float am[8] = {a0.x, a0.y, a0.z, a0.w, a1.x, a1.y, a1.z, a1.w};
            const float bn[8] = {b0.x, b0.y, b0.z, b0.w, b1.x, b1.y, b1.z, b1.w};
            #pragma unroll
            for (int i = 0; i < 8; ++i)
                #pragma unroll
                for (int j = 0; j < 8; ++j)
                    acc[i][j] = fmaf(am[i], bn[j], acc[i][j]);
        }
        if (c + 1 < NLOCAL) sts_chunk((c + 1) & 1);
        GBAR(barid);
    }

    // ---- merge k-split partials ----
    __syncthreads();
    if (gid == 1) {
        #pragma unroll
        for (int i = 0; i < 8; ++i)
            #pragma unroll
            for (int j = 0; j < 8; ++j)
                smem[gtid * 65 + i * 8 + j] = acc[i][j];
    }
    __syncthreads();
    if (gid != 0) return;

    #pragma unroll
    for (int i = 0; i < 8; ++i)
        #pragma unroll
        for (int j = 0; j < 8; ++j)
            acc[i][j] += smem[gtid * 65 + i * 8 + j];
    GBAR(1);

    // ---- dump summed logits [token][expert] ----
    #pragma unroll
    for (int i = 0; i < 8; ++i)
        #pragma unroll
        for (int j = 0; j < 8; ++j)
            smem[(tym * 8 + i) * LG_STRIDE + txk * 8 + j] = acc[i][j];
    GBAR(1);

    // ---- exact per-token epilogue: thread gtid owns token bm+gtid ----
    const float4* b4 = (const float4*)bias;
    const float4* lrow = (const float4*)&smem[gtid * LG_STRIDE];

    float v[64];
    #pragma unroll
    for (int q = 0; q < 16; ++q) {
        const float4 lv = lrow[q];
        const float4 bv = __ldg(b4 + q);
        v[q * 4 + 0] = lv.x + bv.x;
        v[q * 4 + 1] = lv.y + bv.y;
        v[q * 4 + 2] = lv.z + bv.z;
        v[q * 4 + 3] = lv.w + bv.w;
    }
    float m1 = -INFINITY, m2 = -INFINITY;
    int i1 = 0, i2 = 0;
    #pragma unroll
    for (int e = 0; e < 64; ++e) {
        if (v[e] > m1) { m2 = m1; i2 = i1; m1 = v[e]; i1 = e; }
        else if (v[e] > m2) { m2 = v[e]; i2 = e; }
    }
    float s = 0.0f;
    #pragma unroll
    for (int e = 0; e < 64; ++e) s += __expf(v[e] - m1);

    const float inv = 1.0f / s;
    const int tk = bm + gtid;
    float* oid = out + (size_t)num_tokens * 2;
    *(float2*)&out[tk * 2] = make_float2(inv, __expf(m2 - m1) * inv);
    *(float2*)&oid[tk * 2] = make_float2((float)i1, (float)i2);
}

extern "C" void kernel_launch(void* const* d_in, const int* in_sizes, int n_in,
                              void* d_out, int out_size) {
    const float* x = (const float*)d_in[0];   // [8,4096,1024]
    const float* W = (const float*)d_in[1];   // [64,1024]
    const float* b = (const float*)d_in[2];   // [64]
    float* out = (float*)d_out;

    const int num_tokens = in_sizes[0] / K_DIM;   // 32768
    const int grid = num_tokens / BM;             // 256

    cudaFuncSetAttribute(router_splitk2_kernel,
                         cudaFuncAttributeMaxDynamicSharedMemorySize, SMEM_FLOATS * 4);
    router_splitk2_kernel<<<grid, 256, SMEM_FLOATS * 4>>>(x, W, b, out, num_tokens);
}